// round 3
// baseline (speedup 1.0000x reference)
#include <cuda_runtime.h>

#define NB 8
#define NS 2048
#define ND 768
#define NH 64

// Scratch for projected Q, K, V: [B, N, H] each (4 MB each, static device arrays)
__device__ float g_Q[NB * NS * NH];
__device__ float g_K[NB * NS * NH];
__device__ float g_V[NB * NS * NH];

// ---------------------------------------------------------------------------
// Kernel 1: QKV projection. One GEMM [16384,768] x [768,64] per z-slice.
// Tile: 64 rows x 64 cols x 16 k. 256 threads, each computes a 4x4 microtile.
// ---------------------------------------------------------------------------
__global__ __launch_bounds__(256, 2) void proj_kernel(
    const float* __restrict__ X,
    const float* __restrict__ Wq,
    const float* __restrict__ Wk,
    const float* __restrict__ Wv)
{
    const int z = blockIdx.z;
    const float* __restrict__ W   = (z == 0) ? Wq : (z == 1) ? Wk : Wv;
    float* __restrict__       Out = (z == 0) ? g_Q : (z == 1) ? g_K : g_V;

    __shared__ float As[16][64];   // [k][row] (transposed X tile)
    __shared__ float Bs[16][64];   // [k][col]

    const int row0 = blockIdx.x * 64;
    const int tid  = threadIdx.x;
    const int tx   = tid & 15;     // col group
    const int ty   = tid >> 4;     // row group

    const int lr  = tid >> 2;          // 0..63 : X row to load
    const int lk4 = (tid & 3) * 4;     // k offset within tile
    const int wk  = tid >> 4;          // 0..15 : W row to load
    const int wc  = (tid & 15) * 4;    // W col offset

    float acc[4][4];
#pragma unroll
    for (int i = 0; i < 4; ++i)
#pragma unroll
        for (int j = 0; j < 4; ++j) acc[i][j] = 0.0f;

    for (int kk = 0; kk < ND; kk += 16) {
        {
            float4 xa = *reinterpret_cast<const float4*>(
                X + (size_t)(row0 + lr) * ND + kk + lk4);
            As[lk4 + 0][lr] = xa.x;
            As[lk4 + 1][lr] = xa.y;
            As[lk4 + 2][lr] = xa.z;
            As[lk4 + 3][lr] = xa.w;
        }
        {
            *reinterpret_cast<float4*>(&Bs[wk][wc]) =
                *reinterpret_cast<const float4*>(W + (size_t)(kk + wk) * NH + wc);
        }
        __syncthreads();

#pragma unroll
        for (int k = 0; k < 16; ++k) {
            float a[4];
#pragma unroll
            for (int i = 0; i < 4; ++i) a[i] = As[k][ty * 4 + i];
            float4 bv = *reinterpret_cast<const float4*>(&Bs[k][tx * 4]);
#pragma unroll
            for (int i = 0; i < 4; ++i) {
                acc[i][0] = fmaf(a[i], bv.x, acc[i][0]);
                acc[i][1] = fmaf(a[i], bv.y, acc[i][1]);
                acc[i][2] = fmaf(a[i], bv.z, acc[i][2]);
                acc[i][3] = fmaf(a[i], bv.w, acc[i][3]);
            }
        }
        __syncthreads();
    }

#pragma unroll
    for (int i = 0; i < 4; ++i) {
        float4 r = make_float4(acc[i][0], acc[i][1], acc[i][2], acc[i][3]);
        *reinterpret_cast<float4*>(
            Out + (size_t)(row0 + ty * 4 + i) * NH + tx * 4) = r;
    }
}

// ---------------------------------------------------------------------------
// Kernel 2: causal flash attention with online softmax.
// Block: 64 queries, 128 threads -> 2 threads per query (key-split halves).
// K/V tiles of 64 keys in smem; chunks of 16 keys (8 per sub-thread) keep the
// score vector in registers. Softmax max is pair-synchronized via shfl each
// chunk so partial (l, o) of the two sub-threads are directly summable at end.
// Block order reversed so long (high-q) blocks are scheduled first.
// ---------------------------------------------------------------------------
__global__ __launch_bounds__(128, 2) void attn_kernel(float* __restrict__ out)
{
    const int b   = blockIdx.y;
    const int qt  = (gridDim.x - 1) - blockIdx.x;   // big tiles launch first
    const int q0  = qt * 64;
    const int tid = threadIdx.x;
    const int ql  = tid >> 1;      // local query 0..63
    const int sub = tid & 1;       // which key-half of each chunk
    const int q_idx = q0 + ql;

    __shared__ float Ks[64][64];
    __shared__ float Vs[64][64];

    const float* __restrict__ Qb = g_Q + (size_t)b * NS * NH;
    const float* __restrict__ Kb = g_K + (size_t)b * NS * NH;
    const float* __restrict__ Vb = g_V + (size_t)b * NS * NH;

    // q row in registers (16 float4)
    float4 q4[16];
    {
        const float4* qp = reinterpret_cast<const float4*>(Qb + (size_t)q_idx * NH);
#pragma unroll
        for (int u = 0; u < 16; ++u) q4[u] = qp[u];
    }

    float4 o4[16];
#pragma unroll
    for (int u = 0; u < 16; ++u) o4[u] = make_float4(0.f, 0.f, 0.f, 0.f);
    float m = -1e30f;
    float l = 0.0f;

    const int ntiles = qt + 1;
    for (int t = 0; t < ntiles; ++t) {
        const int k0 = t * 64;

        // cooperative K/V tile load: 2 threads per row, 8 float4 each
        {
            const int r = tid >> 1;
            const int c = (tid & 1) * 8;
            const float4* ks = reinterpret_cast<const float4*>(Kb + (size_t)(k0 + r) * NH);
            const float4* vs = reinterpret_cast<const float4*>(Vb + (size_t)(k0 + r) * NH);
            float4* kd = reinterpret_cast<float4*>(&Ks[r][0]);
            float4* vd = reinterpret_cast<float4*>(&Vs[r][0]);
#pragma unroll
            for (int u = 0; u < 8; ++u) {
                kd[c + u] = ks[c + u];
                vd[c + u] = vs[c + u];
            }
        }
        __syncthreads();

#pragma unroll 1
        for (int ch = 0; ch < 4; ++ch) {
            const int jb = ch * 16 + sub * 8;   // this thread's 8 keys (local idx)

            float s[8];
            float cmax = -1e30f;
#pragma unroll
            for (int jj = 0; jj < 8; ++jj) {
                const float4* kr = reinterpret_cast<const float4*>(&Ks[jb + jj][0]);
                float a0 = 0.f, a1 = 0.f;
#pragma unroll
                for (int d = 0; d < 16; ++d) {
                    float4 kv = kr[d];            // warp-broadcast LDS.128
                    a0 = fmaf(q4[d].x, kv.x, a0);
                    a1 = fmaf(q4[d].y, kv.y, a1);
                    a0 = fmaf(q4[d].z, kv.z, a0);
                    a1 = fmaf(q4[d].w, kv.w, a1);
                }
                float sv = (k0 + jb + jj <= q_idx) ? (a0 + a1) * 0.125f : -1e30f;
                s[jj] = sv;
                cmax  = fmaxf(cmax, sv);
            }

            // pair-shared running max (lanes fully converged -> full mask OK)
            float pm    = fmaxf(cmax, __shfl_xor_sync(0xffffffffu, cmax, 1));
            float m_new = fmaxf(m, pm);
            float corr  = __expf(m - m_new);      // exp(-1e30-x) -> 0 first time
            m = m_new;
            l *= corr;
#pragma unroll
            for (int u = 0; u < 16; ++u) {
                o4[u].x *= corr; o4[u].y *= corr;
                o4[u].z *= corr; o4[u].w *= corr;
            }

#pragma unroll
            for (int jj = 0; jj < 8; ++jj) {
                float p = __expf(s[jj] - m_new);  // masked -> exp(-1e30) = 0
                l += p;
                const float4* vr = reinterpret_cast<const float4*>(&Vs[jb + jj][0]);
#pragma unroll
                for (int u = 0; u < 16; ++u) {
                    float4 vv = vr[u];            // warp-broadcast LDS.128
                    o4[u].x = fmaf(p, vv.x, o4[u].x);
                    o4[u].y = fmaf(p, vv.y, o4[u].y);
                    o4[u].z = fmaf(p, vv.z, o4[u].z);
                    o4[u].w = fmaf(p, vv.w, o4[u].w);
                }
            }
        }
        __syncthreads();
    }

    // merge the two sub-threads of each query: m was kept identical, so the
    // partial (l, o) just add.
    l += __shfl_xor_sync(0xffffffffu, l, 1);
    float invl = 1.0f / l;

    float* op = out + ((size_t)b * NS + q_idx) * NH;
#pragma unroll
    for (int u = 0; u < 16; ++u) {
        float4 v = o4[u];
        v.x += __shfl_xor_sync(0xffffffffu, v.x, 1);
        v.y += __shfl_xor_sync(0xffffffffu, v.y, 1);
        v.z += __shfl_xor_sync(0xffffffffu, v.z, 1);
        v.w += __shfl_xor_sync(0xffffffffu, v.w, 1);
        if ((u >> 3) == sub) {   // each sub-thread stores its half of the row
            v.x *= invl; v.y *= invl; v.z *= invl; v.w *= invl;
            *reinterpret_cast<float4*>(op + u * 4) = v;
        }
    }
}

// ---------------------------------------------------------------------------
extern "C" void kernel_launch(void* const* d_in, const int* in_sizes, int n_in,
                              void* d_out, int out_size)
{
    const float* X  = (const float*)d_in[0];
    const float* Wq = (const float*)d_in[1];
    const float* Wk = (const float*)d_in[2];
    const float* Wv = (const float*)d_in[3];
    float* out = (float*)d_out;

    // QKV projection: M = B*N = 16384 rows, 64 rows per block, 3 weight slices
    proj_kernel<<<dim3((NB * NS) / 64, 1, 3), 256>>>(X, Wq, Wk, Wv);

    // Attention: 32 q-tiles of 64 per batch, 8 batches
    attn_kernel<<<dim3(NS / 64, NB), 128>>>(out);
}

// round 4
// speedup vs baseline: 1.7034x; 1.7034x over previous
#include <cuda_runtime.h>

#define NB 8
#define NS 2048
#define ND 768
#define NH 64
#define SK 68          // padded smem row stride (floats); 68*4B = 272B, 16B-aligned

__device__ float g_Q[NB * NS * NH];
__device__ float g_K[NB * NS * NH];
__device__ float g_V[NB * NS * NH];

// ---------------------------------------------------------------------------
// Kernel 1: QKV projection. [16384,768] x [768,64] per z-slice.
// 64x64x16 tiles, 256 threads, 4x4 microtiles, all-float4 smem reads.
// ---------------------------------------------------------------------------
__global__ __launch_bounds__(256, 2) void proj_kernel(
    const float* __restrict__ X,
    const float* __restrict__ Wq,
    const float* __restrict__ Wk,
    const float* __restrict__ Wv)
{
    const int z = blockIdx.z;
    const float* __restrict__ W   = (z == 0) ? Wq : (z == 1) ? Wk : Wv;
    float* __restrict__       Out = (z == 0) ? g_Q : (z == 1) ? g_K : g_V;

    __shared__ float As[16][64];   // [k][row] (transposed X tile)
    __shared__ float Bs[16][64];   // [k][col]

    const int row0 = blockIdx.x * 64;
    const int tid  = threadIdx.x;
    const int tx   = tid & 15;
    const int ty   = tid >> 4;

    const int lr  = tid >> 2;
    const int lk4 = (tid & 3) * 4;
    const int wk  = tid >> 4;
    const int wc  = (tid & 15) * 4;

    float acc[4][4];
#pragma unroll
    for (int i = 0; i < 4; ++i)
#pragma unroll
        for (int j = 0; j < 4; ++j) acc[i][j] = 0.0f;

    for (int kk = 0; kk < ND; kk += 16) {
        {
            float4 xa = *reinterpret_cast<const float4*>(
                X + (size_t)(row0 + lr) * ND + kk + lk4);
            As[lk4 + 0][lr] = xa.x;
            As[lk4 + 1][lr] = xa.y;
            As[lk4 + 2][lr] = xa.z;
            As[lk4 + 3][lr] = xa.w;
        }
        {
            *reinterpret_cast<float4*>(&Bs[wk][wc]) =
                *reinterpret_cast<const float4*>(W + (size_t)(kk + wk) * NH + wc);
        }
        __syncthreads();

#pragma unroll
        for (int k = 0; k < 16; ++k) {
            float4 av = *reinterpret_cast<const float4*>(&As[k][ty * 4]);
            float4 bv = *reinterpret_cast<const float4*>(&Bs[k][tx * 4]);
            acc[0][0] = fmaf(av.x, bv.x, acc[0][0]);
            acc[0][1] = fmaf(av.x, bv.y, acc[0][1]);
            acc[0][2] = fmaf(av.x, bv.z, acc[0][2]);
            acc[0][3] = fmaf(av.x, bv.w, acc[0][3]);
            acc[1][0] = fmaf(av.y, bv.x, acc[1][0]);
            acc[1][1] = fmaf(av.y, bv.y, acc[1][1]);
            acc[1][2] = fmaf(av.y, bv.z, acc[1][2]);
            acc[1][3] = fmaf(av.y, bv.w, acc[1][3]);
            acc[2][0] = fmaf(av.z, bv.x, acc[2][0]);
            acc[2][1] = fmaf(av.z, bv.y, acc[2][1]);
            acc[2][2] = fmaf(av.z, bv.z, acc[2][2]);
            acc[2][3] = fmaf(av.z, bv.w, acc[2][3]);
            acc[3][0] = fmaf(av.w, bv.x, acc[3][0]);
            acc[3][1] = fmaf(av.w, bv.y, acc[3][1]);
            acc[3][2] = fmaf(av.w, bv.z, acc[3][2]);
            acc[3][3] = fmaf(av.w, bv.w, acc[3][3]);
        }
        __syncthreads();
    }

#pragma unroll
    for (int i = 0; i < 4; ++i) {
        float4 r = make_float4(acc[i][0], acc[i][1], acc[i][2], acc[i][3]);
        *reinterpret_cast<float4*>(
            Out + (size_t)(row0 + ty * 4 + i) * NH + tx * 4) = r;
    }
}

// ---------------------------------------------------------------------------
// Kernel 2: causal flash attention, GEMM-style register blocking.
// Block = 64 queries, 256 threads. Each thread owns a 4x4 microtile of the
// 64x64 score tile S and a 4x4 microtile of the 64x64 output O.
//   S = Q K^T : Qs[d][q], Ks[d][k] in smem (d-major), 16 FMA / 2 LDS.128.
//   softmax   : row state (m) reduced across the 16-lane tx-group via shfl;
//               l kept as per-thread partial, reduced once at the end.
//   O += P V  : P written transposed into the K buffer (aliased), Vs natural.
// Reversed block order: long (high-q) tiles first for causal load balance.
// ---------------------------------------------------------------------------
__global__ __launch_bounds__(256, 2) void attn_kernel(float* __restrict__ out)
{
    extern __shared__ float sm[];
    float* __restrict__ Qs = sm;                // [64][SK]  Q, d-major
    float* __restrict__ KP = sm + 64 * SK;      // [64][SK]  K (d-major) / P (k-major)
    float* __restrict__ Vs = sm + 2 * 64 * SK;  // [64][SK]  V, natural

    const int b   = blockIdx.y;
    const int qt  = (gridDim.x - 1) - blockIdx.x;
    const int q0  = qt * 64;
    const int tid = threadIdx.x;
    const int tx  = tid & 15;
    const int ty  = tid >> 4;

    const float* __restrict__ Qb = g_Q + (size_t)b * NS * NH;
    const float* __restrict__ Kb = g_K + (size_t)b * NS * NH;
    const float* __restrict__ Vb = g_V + (size_t)b * NS * NH;

    // Load Q tile once, transposed -> Qs[d][q]
    {
        const int r  = tid >> 2;
        const int dg = (tid & 3) * 16;
        const float4* qp = reinterpret_cast<const float4*>(Qb + (size_t)(q0 + r) * NH + dg);
#pragma unroll
        for (int u = 0; u < 4; ++u) {
            float4 v = qp[u];
            const int d = dg + u * 4;
            Qs[(d + 0) * SK + r] = v.x;
            Qs[(d + 1) * SK + r] = v.y;
            Qs[(d + 2) * SK + r] = v.z;
            Qs[(d + 3) * SK + r] = v.w;
        }
    }

    float o[4][4];
#pragma unroll
    for (int i = 0; i < 4; ++i)
#pragma unroll
        for (int j = 0; j < 4; ++j) o[i][j] = 0.0f;
    float m[4] = {-1e30f, -1e30f, -1e30f, -1e30f};
    float l[4] = {0.f, 0.f, 0.f, 0.f};

    for (int t = 0; t <= qt; ++t) {
        const int k0 = t * 64;

        __syncthreads();   // previous iteration done reading KP(P) and Vs
        // Load K transposed -> KP[d][k], V natural -> Vs[k][h]
        {
            const int r  = tid >> 2;
            const int dg = (tid & 3) * 16;
            const float4* kp = reinterpret_cast<const float4*>(Kb + (size_t)(k0 + r) * NH + dg);
            const float4* vp = reinterpret_cast<const float4*>(Vb + (size_t)(k0 + r) * NH + dg);
#pragma unroll
            for (int u = 0; u < 4; ++u) {
                float4 kv = kp[u];
                const int d = dg + u * 4;
                KP[(d + 0) * SK + r] = kv.x;
                KP[(d + 1) * SK + r] = kv.y;
                KP[(d + 2) * SK + r] = kv.z;
                KP[(d + 3) * SK + r] = kv.w;
                *reinterpret_cast<float4*>(&Vs[r * SK + dg + u * 4]) = vp[u];
            }
        }
        __syncthreads();

        // ---- S = Q K^T (64x64x64, this thread: rows ty*4.., cols tx*4..) ----
        float s[4][4];
#pragma unroll
        for (int i = 0; i < 4; ++i)
#pragma unroll
            for (int j = 0; j < 4; ++j) s[i][j] = 0.0f;

#pragma unroll 4
        for (int d = 0; d < 64; ++d) {
            float4 qv = *reinterpret_cast<const float4*>(&Qs[d * SK + ty * 4]);
            float4 kv = *reinterpret_cast<const float4*>(&KP[d * SK + tx * 4]);
            s[0][0] = fmaf(qv.x, kv.x, s[0][0]);
            s[0][1] = fmaf(qv.x, kv.y, s[0][1]);
            s[0][2] = fmaf(qv.x, kv.z, s[0][2]);
            s[0][3] = fmaf(qv.x, kv.w, s[0][3]);
            s[1][0] = fmaf(qv.y, kv.x, s[1][0]);
            s[1][1] = fmaf(qv.y, kv.y, s[1][1]);
            s[1][2] = fmaf(qv.y, kv.z, s[1][2]);
            s[1][3] = fmaf(qv.y, kv.w, s[1][3]);
            s[2][0] = fmaf(qv.z, kv.x, s[2][0]);
            s[2][1] = fmaf(qv.z, kv.y, s[2][1]);
            s[2][2] = fmaf(qv.z, kv.z, s[2][2]);
            s[2][3] = fmaf(qv.z, kv.w, s[2][3]);
            s[3][0] = fmaf(qv.w, kv.x, s[3][0]);
            s[3][1] = fmaf(qv.w, kv.y, s[3][1]);
            s[3][2] = fmaf(qv.w, kv.z, s[3][2]);
            s[3][3] = fmaf(qv.w, kv.w, s[3][3]);
        }

        // scale; causal mask only on the diagonal tile
#pragma unroll
        for (int i = 0; i < 4; ++i)
#pragma unroll
            for (int j = 0; j < 4; ++j) s[i][j] *= 0.125f;
        if (t == qt) {
#pragma unroll
            for (int i = 0; i < 4; ++i)
#pragma unroll
                for (int j = 0; j < 4; ++j)
                    if (tx * 4 + j > ty * 4 + i) s[i][j] = -1e30f;
        }

        // ---- online softmax: row max over the 16-lane tx-group ----
        float rm[4];
#pragma unroll
        for (int i = 0; i < 4; ++i)
            rm[i] = fmaxf(fmaxf(s[i][0], s[i][1]), fmaxf(s[i][2], s[i][3]));
#pragma unroll
        for (int off = 8; off >= 1; off >>= 1) {
#pragma unroll
            for (int i = 0; i < 4; ++i)
                rm[i] = fmaxf(rm[i], __shfl_xor_sync(0xffffffffu, rm[i], off));
        }

        float corr[4];
#pragma unroll
        for (int i = 0; i < 4; ++i) {
            float mn = fmaxf(m[i], rm[i]);
            corr[i]  = __expf(m[i] - mn);   // 0 on first tile (m = -1e30)
            m[i]     = mn;
        }
#pragma unroll
        for (int i = 0; i < 4; ++i) {
            l[i] *= corr[i];
            o[i][0] *= corr[i]; o[i][1] *= corr[i];
            o[i][2] *= corr[i]; o[i][3] *= corr[i];
        }
#pragma unroll
        for (int i = 0; i < 4; ++i) {
#pragma unroll
            for (int j = 0; j < 4; ++j)
                s[i][j] = __expf(s[i][j] - m[i]);   // masked -> exp(-1e30) = 0
            l[i] += s[i][0] + s[i][1] + s[i][2] + s[i][3];
        }

        __syncthreads();   // all warps done reading KP as Ks
        // write P transposed into KP: KP[k][q], float4 along q
#pragma unroll
        for (int j = 0; j < 4; ++j) {
            *reinterpret_cast<float4*>(&KP[(tx * 4 + j) * SK + ty * 4]) =
                make_float4(s[0][j], s[1][j], s[2][j], s[3][j]);
        }
        __syncthreads();

        // ---- O += P V (64x64x64, this thread: rows ty*4.., cols tx*4..) ----
#pragma unroll 4
        for (int k = 0; k < 64; ++k) {
            float4 pv = *reinterpret_cast<const float4*>(&KP[k * SK + ty * 4]);
            float4 vv = *reinterpret_cast<const float4*>(&Vs[k * SK + tx * 4]);
            o[0][0] = fmaf(pv.x, vv.x, o[0][0]);
            o[0][1] = fmaf(pv.x, vv.y, o[0][1]);
            o[0][2] = fmaf(pv.x, vv.z, o[0][2]);
            o[0][3] = fmaf(pv.x, vv.w, o[0][3]);
            o[1][0] = fmaf(pv.y, vv.x, o[1][0]);
            o[1][1] = fmaf(pv.y, vv.y, o[1][1]);
            o[1][2] = fmaf(pv.y, vv.z, o[1][2]);
            o[1][3] = fmaf(pv.y, vv.w, o[1][3]);
            o[2][0] = fmaf(pv.z, vv.x, o[2][0]);
            o[2][1] = fmaf(pv.z, vv.y, o[2][1]);
            o[2][2] = fmaf(pv.z, vv.z, o[2][2]);
            o[2][3] = fmaf(pv.z, vv.w, o[2][3]);
            o[3][0] = fmaf(pv.w, vv.x, o[3][0]);
            o[3][1] = fmaf(pv.w, vv.y, o[3][1]);
            o[3][2] = fmaf(pv.w, vv.z, o[3][2]);
            o[3][3] = fmaf(pv.w, vv.w, o[3][3]);
        }
    }

    // finalize: reduce per-thread partial l across the tx-group, normalize, store
#pragma unroll
    for (int off = 8; off >= 1; off >>= 1) {
#pragma unroll
        for (int i = 0; i < 4; ++i)
            l[i] += __shfl_xor_sync(0xffffffffu, l[i], off);
    }

    float* op = out + ((size_t)b * NS + q0) * NH;
#pragma unroll
    for (int i = 0; i < 4; ++i) {
        float inv = 1.0f / l[i];
        float4 r = make_float4(o[i][0] * inv, o[i][1] * inv,
                               o[i][2] * inv, o[i][3] * inv);
        *reinterpret_cast<float4*>(op + (size_t)(ty * 4 + i) * NH + tx * 4) = r;
    }
}

// ---------------------------------------------------------------------------
extern "C" void kernel_launch(void* const* d_in, const int* in_sizes, int n_in,
                              void* d_out, int out_size)
{
    const float* X  = (const float*)d_in[0];
    const float* Wq = (const float*)d_in[1];
    const float* Wk = (const float*)d_in[2];
    const float* Wv = (const float*)d_in[3];
    float* out = (float*)d_out;

    const int attn_smem = 3 * 64 * SK * (int)sizeof(float);   // 52224 B
    cudaFuncSetAttribute(attn_kernel,
                         cudaFuncAttributeMaxDynamicSharedMemorySize, attn_smem);

    proj_kernel<<<dim3((NB * NS) / 64, 1, 3), 256>>>(X, Wq, Wk, Wv);
    attn_kernel<<<dim3(NS / 64, NB), 256, attn_smem>>>(out);
}